// round 11
// baseline (speedup 1.0000x reference)
#include <cuda_runtime.h>
#include <cuda_fp16.h>

#define F_IN 128
#define FS   64
#define NH   8
#define NMAX 4096

// persistent scratch (allocations forbidden)
__device__ __half   g_hh[NMAX][2 * NH];  // node features fp16, PRE-SCALED by 0.5
__device__ double   g_s1, g_s2;          // gate sum / sum of squares
__device__ unsigned g_done = 0;          // last-block ticket (kernel B)

__device__ __forceinline__ unsigned h2_to_u(__half2 h) { return *(unsigned*)&h; }
__device__ __forceinline__ __half2 u_to_h2(unsigned u) { return *(__half2*)&u; }
// packed pair of tanh.approx on fp16x2 : one MUFU op for two activations
__device__ __forceinline__ __half2 tanh2_fast(__half2 x) {
    unsigned r, xi = h2_to_u(x);
    asm("tanh.approx.f16x2 %0, %1;" : "=r"(r) : "r"(xi));
    return u_to_h2(r);
}

// ---------------------------------------------------------------------------
// Kernel A: prep (redundant per block) + node features.  512 thr, 32 nodes/blk
// ---------------------------------------------------------------------------
__global__ void __launch_bounds__(512)
node_kernel(const float* __restrict__ x,
            const float* __restrict__ Wlin,
            const float* __restrict__ blin,
            const float* __restrict__ W1,
            const float* __restrict__ b1,
            int N) {
    __shared__ float WlinS[FS][F_IN];     // 32 KB
    __shared__ float Ms[F_IN][2 * NH];    // fused weight, [k][t]
    __shared__ float cs[2 * NH];          // fused bias
    __shared__ float W1s[NH][2 * FS];     // 4 KB

    const int tid = threadIdx.x;

    // stage Wlin (coalesced float4) + W1
    {
        const float4* src = (const float4*)Wlin;
        float4* dst = (float4*)&WlinS[0][0];
        #pragma unroll
        for (int r = 0; r < 4; r++) dst[tid + 512 * r] = src[tid + 512 * r];
    }
    {
        W1s[tid >> 7][(tid & 127)]       = W1[tid];
        W1s[(tid + 512) >> 7][tid & 127] = W1[tid + 512];
    }
    if (blockIdx.x == 0 && tid == 0) { g_s1 = 0.0; g_s2 = 0.0; }
    __syncthreads();

    // prep: M = W1 @ Wlin  (512 threads, 4 k-columns each)
    {
        int t  = tid & 15;
        int k4 = tid >> 4;                 // 0..31 -> columns 4*k4..4*k4+3
        int hrow = t & (NH - 1);
        int off  = (t < NH) ? 0 : FS;
        float a0 = 0.f, a1 = 0.f, a2 = 0.f, a3 = 0.f;
        #pragma unroll 8
        for (int f = 0; f < FS; f++) {
            float4 wl = *(const float4*)&WlinS[f][k4 * 4];
            float w1v = W1s[hrow][off + f];
            a0 = fmaf(w1v, wl.x, a0);
            a1 = fmaf(w1v, wl.y, a1);
            a2 = fmaf(w1v, wl.z, a2);
            a3 = fmaf(w1v, wl.w, a3);
        }
        Ms[4 * k4 + 0][t] = a0;
        Ms[4 * k4 + 1][t] = a1;
        Ms[4 * k4 + 2][t] = a2;
        Ms[4 * k4 + 3][t] = a3;
    }
    if (tid < 2 * NH) {
        int t = tid, hrow = t & (NH - 1), off = (t < NH) ? 0 : FS;
        float acc = (t < NH) ? b1[t] : 0.0f;
        for (int f = 0; f < FS; f++)
            acc = fmaf(W1s[hrow][off + f], blin[f], acc);
        cs[t] = acc;
    }
    __syncthreads();

    // node features: one (node, t) per thread; 32 nodes per block
    {
        int g = tid >> 4;                  // 0..31
        int t = tid & 15;
        int node = blockIdx.x * 32 + g;
        bool valid = (node < N);
        float acc = 0.0f;
        if (valid) {
            const float4* xr = (const float4*)(x + (size_t)node * F_IN);
            float b0 = 0.f, b1a = 0.f, b2a = 0.f, b3 = 0.f;
            #pragma unroll
            for (int k4 = 0; k4 < F_IN / 4; k4 += 4) {
                float4 v0 = xr[k4 + 0], v1 = xr[k4 + 1];
                float4 v2 = xr[k4 + 2], v3 = xr[k4 + 3];
                b0 = fmaf(v0.x, Ms[4*k4+ 0][t], b0); b0 = fmaf(v0.y, Ms[4*k4+ 1][t], b0);
                b0 = fmaf(v0.z, Ms[4*k4+ 2][t], b0); b0 = fmaf(v0.w, Ms[4*k4+ 3][t], b0);
                b1a= fmaf(v1.x, Ms[4*k4+ 4][t], b1a);b1a= fmaf(v1.y, Ms[4*k4+ 5][t], b1a);
                b1a= fmaf(v1.z, Ms[4*k4+ 6][t], b1a);b1a= fmaf(v1.w, Ms[4*k4+ 7][t], b1a);
                b2a= fmaf(v2.x, Ms[4*k4+ 8][t], b2a);b2a= fmaf(v2.y, Ms[4*k4+ 9][t], b2a);
                b2a= fmaf(v2.z, Ms[4*k4+10][t], b2a);b2a= fmaf(v2.w, Ms[4*k4+11][t], b2a);
                b3 = fmaf(v3.x, Ms[4*k4+12][t], b3); b3 = fmaf(v3.y, Ms[4*k4+13][t], b3);
                b3 = fmaf(v3.z, Ms[4*k4+14][t], b3); b3 = fmaf(v3.w, Ms[4*k4+15][t], b3);
            }
            acc = 0.5f * (cs[t] + ((b0 + b1a) + (b2a + b3)));   // pre-scale by 0.5
        }
        float accN = __shfl_down_sync(0xffffffffu, acc, 1);
        if (valid && !(t & 1))
            ((__half2*)g_hh[node])[t >> 1] = __floats2half2_rn(acc, accN);
    }
}

// ---------------------------------------------------------------------------
// Kernel B: edges + variance.  Full g_hh table staged in SMEM (128 KB);
// scattered gathers become LDS instead of L1tex wavefront storms.
// PDL: ei/u prologue overlaps with kernel A.
// ---------------------------------------------------------------------------
__global__ void __launch_bounds__(1024)
edge_kernel(const int*   __restrict__ ei,
            const float* __restrict__ u,
            const float* __restrict__ W2,
            const float* __restrict__ b2,
            float* __restrict__ out,
            int E, int out_size, int nblk) {
    extern __shared__ __align__(16) uint4 tbl[];   // NMAX*2 uint4 = 128 KB
    __shared__ float r1[32], r2[32];

    const int tid = threadIdx.x;
    const int e0  = blockIdx.x * 1024 + tid;

    // ---- PDL prologue: everything independent of g_hh ----
    int   i = 0, j = 0;
    float uu = 0.0f;
    if (e0 < E) { i = ei[e0]; j = ei[E + e0]; uu = u[e0]; }

    __half2 w2p[NH / 2];
    #pragma unroll
    for (int q = 0; q < NH / 2; q++)
        w2p[q] = __floats2half2_rn(0.25f * W2[2 * q], 0.25f * W2[2 * q + 1]);
    float b2p = 0.5f * b2[0];
    #pragma unroll
    for (int h = 0; h < NH; h++) b2p += 0.25f * W2[h];

    // precompute the u-dependent part of the gate
    float eps     = fmaf(-0.9998f, uu, 0.9999f);
    float onemeps = fmaf( 0.9998f, uu, 0.0001f);
    float qr  = __fdividef(onemeps, eps);
    float q2  = qr * qr;

    // ---- wait for kernel A's g_hh stores (implicit completion trigger) ----
    cudaGridDependencySynchronize();

    // ---- stage the whole node-feature table into smem (coalesced) ----
    {
        const uint4* src = (const uint4*)g_hh;     // NMAX*2 = 8192 uint4
        #pragma unroll
        for (int r = 0; r < (NMAX * 2) / 1024; r++)
            tbl[tid + 1024 * r] = src[tid + 1024 * r];
    }
    __syncthreads();

    float ls1 = 0.0f, ls2 = 0.0f;
    if (e0 < E) {
        uint4 i_lo = tbl[2 * i], i_hi = tbl[2 * i + 1];
        uint4 j_lo = tbl[2 * j], j_hi = tbl[2 * j + 1];

        const __half2* il = (const __half2*)&i_lo;
        const __half2* ih = (const __half2*)&i_hi;
        const __half2* jl = (const __half2*)&j_lo;
        const __half2* jh = (const __half2*)&j_hi;

        // accumulate sij/2 and sji/2 in half2 (w2p = w2/4, g_hh = h/2)
        __half2 aij = __floats2half2_rn(0.0f, 0.0f);
        __half2 aji = aij;
        #pragma unroll
        for (int q = 0; q < 4; q++) {
            __half2 ta = tanh2_fast(__hadd2(il[q], jh[q]));
            __half2 tc = tanh2_fast(__hadd2(jl[q], ih[q]));
            aij = __hfma2(w2p[q], ta, aij);
            aji = __hfma2(w2p[q], tc, aji);
        }
        float2 fij = __half22float2(aij);
        float2 fji = __half22float2(aji);
        float sp_ij = b2p + fij.x + fij.y;   // = sij/2
        float sp_ji = b2p + fji.x + fji.y;   // = sji/2

        // two outer sigmoids in one f16x2 tanh
        __half2 sp = __floats2half2_rn(sp_ij, sp_ji);
        float2 thf = __half22float2(tanh2_fast(sp));
        float w = fmaf(0.25f, thf.x + thf.y, 0.5f);

        // gate = 1/(1 + ((1-eps)/eps)^2 * e^{-2w})
        float a  = q2 * __expf(-2.0f * w);
        float g  = __fdividef(1.0f, 1.0f + a);
        out[e0] = g;
        ls1 = g;
        ls2 = g * g;
    }

    // block reduction of (sum, sumsq)
    #pragma unroll
    for (int o = 16; o > 0; o >>= 1) {
        ls1 += __shfl_down_sync(0xffffffffu, ls1, o);
        ls2 += __shfl_down_sync(0xffffffffu, ls2, o);
    }
    int lane = tid & 31, wid = tid >> 5;
    if (lane == 0) { r1[wid] = ls1; r2[wid] = ls2; }
    __syncthreads();
    if (tid < 32) {
        float a = r1[tid], b = r2[tid];
        #pragma unroll
        for (int o = 16; o > 0; o >>= 1) {
            a += __shfl_down_sync(0xffffffffu, a, o);
            b += __shfl_down_sync(0xffffffffu, b, o);
        }
        if (tid == 0) {
            atomicAdd(&g_s1, (double)a);
            atomicAdd(&g_s2, (double)b);
            __threadfence();
            // last block computes the variance
            if (atomicAdd(&g_done, 1u) == (unsigned)nblk - 1) {
                g_done = 0;                  // reset for next graph replay
                __threadfence();
                double s1 = atomicAdd(&g_s1, 0.0);
                double s2 = atomicAdd(&g_s2, 0.0);
                double mean = s1 / (double)E;
                out[out_size - 1] = (float)((s2 - s1 * mean) / (double)(E - 1));
            }
        }
    }
}

extern "C" void kernel_launch(void* const* d_in, const int* in_sizes, int n_in,
                              void* d_out, int out_size) {
    const float* x    = (const float*)d_in[0];   // [N, 128]
    const float* Wlin = (const float*)d_in[1];   // [64, 128]
    const float* blin = (const float*)d_in[2];   // [64]
    const float* W1   = (const float*)d_in[3];   // [8, 128]
    const float* b1   = (const float*)d_in[4];   // [8]
    const float* W2   = (const float*)d_in[5];   // [8]
    const float* b2   = (const float*)d_in[6];   // [1]
    const int*   ei   = (const int*)d_in[7];     // [2, E]
    const float* u    = (const float*)d_in[8];   // [E]

    int N = in_sizes[0] / F_IN;
    int E = in_sizes[8];
    float* out = (float*)d_out;

    int blocksA = (N + 31) / 32;
    int blocksB = (E + 1023) / 1024;             // 128 for E=131072
    int smemB   = NMAX * 2 * sizeof(uint4);      // 128 KB

    // host-side attribute set: idempotent, not a stream op (capture-safe)
    static int attr_done = 0;
    if (!attr_done) {
        cudaFuncSetAttribute(edge_kernel,
                             cudaFuncAttributeMaxDynamicSharedMemorySize, smemB);
        attr_done = 1;
    }

    node_kernel<<<blocksA, 512>>>(x, Wlin, blin, W1, b1, N);

    // PDL launch: edge_kernel's prologue overlaps with node_kernel
    cudaLaunchConfig_t cfg = {};
    cfg.gridDim  = dim3((unsigned)blocksB);
    cfg.blockDim = dim3(1024);
    cfg.dynamicSmemBytes = (size_t)smemB;
    cfg.stream = 0;
    cudaLaunchAttribute attrs[1];
    attrs[0].id = cudaLaunchAttributeProgrammaticStreamSerialization;
    attrs[0].val.programmaticStreamSerializationAllowed = 1;
    cfg.attrs = attrs;
    cfg.numAttrs = 1;
    cudaLaunchKernelEx(&cfg, edge_kernel, ei, u, W2, b2, out, E, out_size, blocksB);
}